// round 14
// baseline (speedup 1.0000x reference)
#include <cuda_runtime.h>

// TiDHy collapses algebraically: r stays zero through the scan, so
//   sl_rhat = sum_t mean_b sum_d (b_sd[d] - X[b,t,d])^2   (all T)
//   sl_rbar = same, t >= 1;  temp_loss = 0, r2_losses = 0, r0/r2 = zeros.
// One fused reduction over X (8 MB) + zero-fill of d_out.
//
// R14: R13 structure (warp-0 tail, no second barrier) + chain shortening:
// 4 parallel body accumulators, float4 LDS for the leader sum, float4
// partial fetch in the tail. Fixed trees -> deterministic.

#define NB 256
#define NT 512

static constexpr int Bc  = 128;                 // batch
static constexpr int Tc  = 32;                  // timesteps
static constexpr int Dc  = 512;                 // input dim
static constexpr int NE4 = Bc * Tc * Dc / 4;    // 524288 float4
static constexpr int GSZ = NB * NT;             // 131072 threads; GSZ*4 == NE4

__device__ float2 g_partials[NB];
__device__ int    g_counter = 0;

__global__ void __launch_bounds__(NT)
tidhy_fused_kernel(const float4* __restrict__ X4,
                   const float4* __restrict__ bsd4,
                   float* __restrict__ out, int out_size)
{
    const int tid  = threadIdx.x;
    const int bid  = blockIdx.x;
    const int gtid = bid * NT + tid;

    // Front-batched independent loads: MLP=4 (16 payload regs).
    float4 x0 = X4[gtid];
    float4 x1 = X4[gtid + GSZ];
    float4 x2 = X4[gtid + 2 * GSZ];
    float4 x3 = X4[gtid + 3 * GSZ];

    // GSZ is a multiple of 128 (=D/4) and 4096 (=D/4*T): d-index and
    // timestep are invariant across this thread's four loads.
    const float4 bs = __ldg(&bsd4[gtid & 127]);

    // Zero the output tuple (out[0..1] overwritten by the finalizer below).
    if (gtid < out_size) out[gtid] = 0.0f;

    // Four independent accumulators -> short dependency chain.
    float dx, dy, dz, dw;
    dx = x0.x - bs.x; dy = x0.y - bs.y; dz = x0.z - bs.z; dw = x0.w - bs.w;
    float s0 = dx * dx + dy * dy + dz * dz + dw * dw;
    dx = x1.x - bs.x; dy = x1.y - bs.y; dz = x1.z - bs.z; dw = x1.w - bs.w;
    float s1 = dx * dx + dy * dy + dz * dz + dw * dw;
    dx = x2.x - bs.x; dy = x2.y - bs.y; dz = x2.z - bs.z; dw = x2.w - bs.w;
    float s2 = dx * dx + dy * dy + dz * dz + dw * dw;
    dx = x3.x - bs.x; dy = x3.y - bs.y; dz = x3.z - bs.z; dw = x3.w - bs.w;
    float s3 = dx * dx + dy * dy + dz * dz + dw * dw;
    float s = (s0 + s1) + (s2 + s3);

    // Warp reduction of s only — t is identical across a warp's 32 lanes,
    // so the t==0 component is derived at the leader.
#pragma unroll
    for (int o = 16; o > 0; o >>= 1)
        s += __shfl_xor_sync(0xFFFFFFFFu, s, o);

    __shared__ __align__(16) float2 s_w[NT / 32];
    const int wid = tid >> 5;
    const int lid = tid & 31;
    if (lid == 0) {
        const bool is_t0 = (((gtid >> 7) & (Tc - 1)) == 0);
        s_w[wid] = make_float2(s, is_t0 ? s : 0.0f);
    }
    __syncthreads();

    if (wid == 0) {
        int last = 0;
        if (lid == 0) {
            // Leader sum of 16 float2 slots as 8 x LDS.128, pairwise tree.
            const float4* sw4 = reinterpret_cast<const float4*>(s_w);
            float vx = 0.0f, vy = 0.0f;
#pragma unroll
            for (int w = 0; w < NT / 64; w++) {
                float4 a = sw4[w];
                vx += a.x + a.z;
                vy += a.y + a.w;
            }
            g_partials[bid] = make_float2(vx, vy);
            // Release-increment orders the partial store before the bump.
            int old;
            asm volatile("atom.release.gpu.global.add.s32 %0, [%1], 1;"
                         : "=r"(old) : "l"(&g_counter) : "memory");
            last = (old == NB - 1) ? 1 : 0;
        }
        // Warp-local broadcast: no smem, no block barrier.
        last = __shfl_sync(0xFFFFFFFFu, last, 0);

        if (last) {
            // Final reduction entirely in warp 0 of the last-arriving block.
            asm volatile("fence.acquire.gpu;" ::: "memory");
            const float4* gp4 = reinterpret_cast<const float4*>(g_partials);
            float ft = 0.0f, f0 = 0.0f;
#pragma unroll
            for (int k = 0; k < NB / 64; k++) {      // 4 float4 per lane
                float4 a = gp4[k * 32 + lid];
                ft += a.x + a.z;
                f0 += a.y + a.w;
            }
#pragma unroll
            for (int o = 16; o > 0; o >>= 1) {
                ft += __shfl_xor_sync(0xFFFFFFFFu, ft, o);
                f0 += __shfl_xor_sync(0xFFFFFFFFu, f0, o);
            }
            if (lid == 0) {
                out[0] = ft / (float)Bc;          // sl_rhat (all t)
                out[1] = (ft - f0) / (float)Bc;   // sl_rbar (t >= 1)
                g_counter = 0;                    // reset for next graph replay
            }
        }
    }
}

extern "C" void kernel_launch(void* const* d_in, const int* in_sizes, int n_in,
                              void* d_out, int out_size)
{
    const float4* X4   = (const float4*)d_in[0];
    const float4* bsd4 = (const float4*)d_in[3];
    float* out = (float*)d_out;

    tidhy_fused_kernel<<<NB, NT>>>(X4, bsd4, out, out_size);
}

// round 15
// speedup vs baseline: 1.0749x; 1.0749x over previous
#include <cuda_runtime.h>

// TiDHy collapses algebraically: r stays zero through the scan, so
//   sl_rhat = sum_t mean_b sum_d (b_sd[d] - X[b,t,d])^2   (all T)
//   sl_rbar = same, t >= 1;  temp_loss = 0, r2_losses = 0, r0/r2 = zeros.
// One fused reduction over X (8 MB) + zero-fill of d_out.
//
// R15: best-draw configuration (R13: 256x512, warp-0 tail, no second
// barrier, scalar leader sum) + R14's riskless 4-accumulator body tree.
// Deterministic fixed-tree summation (rel_err 0.0).

#define NB 256
#define NT 512

static constexpr int Bc  = 128;                 // batch
static constexpr int Tc  = 32;                  // timesteps
static constexpr int Dc  = 512;                 // input dim
static constexpr int NE4 = Bc * Tc * Dc / 4;    // 524288 float4
static constexpr int GSZ = NB * NT;             // 131072 threads; GSZ*4 == NE4

__device__ float2 g_partials[NB];
__device__ int    g_counter = 0;

__global__ void __launch_bounds__(NT)
tidhy_fused_kernel(const float4* __restrict__ X4,
                   const float4* __restrict__ bsd4,
                   float* __restrict__ out, int out_size)
{
    const int tid  = threadIdx.x;
    const int bid  = blockIdx.x;
    const int gtid = bid * NT + tid;

    // Front-batched independent loads: MLP=4 (16 payload regs).
    float4 x0 = X4[gtid];
    float4 x1 = X4[gtid + GSZ];
    float4 x2 = X4[gtid + 2 * GSZ];
    float4 x3 = X4[gtid + 3 * GSZ];

    // GSZ is a multiple of 128 (=D/4) and 4096 (=D/4*T): d-index and
    // timestep are invariant across this thread's four loads.
    const float4 bs = __ldg(&bsd4[gtid & 127]);

    // Zero the output tuple (out[0..1] overwritten by the finalizer below).
    if (gtid < out_size) out[gtid] = 0.0f;

    // Four independent accumulators -> short dependency chain.
    float dx, dy, dz, dw;
    dx = x0.x - bs.x; dy = x0.y - bs.y; dz = x0.z - bs.z; dw = x0.w - bs.w;
    float s0 = dx * dx + dy * dy + dz * dz + dw * dw;
    dx = x1.x - bs.x; dy = x1.y - bs.y; dz = x1.z - bs.z; dw = x1.w - bs.w;
    float s1 = dx * dx + dy * dy + dz * dz + dw * dw;
    dx = x2.x - bs.x; dy = x2.y - bs.y; dz = x2.z - bs.z; dw = x2.w - bs.w;
    float s2 = dx * dx + dy * dy + dz * dz + dw * dw;
    dx = x3.x - bs.x; dy = x3.y - bs.y; dz = x3.z - bs.z; dw = x3.w - bs.w;
    float s3 = dx * dx + dy * dy + dz * dz + dw * dw;
    float s = (s0 + s1) + (s2 + s3);

    // Warp reduction of s only — t is identical across a warp's 32 lanes,
    // so the t==0 component is derived at the leader.
#pragma unroll
    for (int o = 16; o > 0; o >>= 1)
        s += __shfl_xor_sync(0xFFFFFFFFu, s, o);

    __shared__ float2 s_w[NT / 32];
    const int wid = tid >> 5;
    const int lid = tid & 31;
    if (lid == 0) {
        const bool is_t0 = (((gtid >> 7) & (Tc - 1)) == 0);
        s_w[wid] = make_float2(s, is_t0 ? s : 0.0f);
    }
    __syncthreads();

    if (wid == 0) {
        int last = 0;
        if (lid == 0) {
            // Serial leader sum of 16 float2 smem slots (pipelined LDS).
            float2 v = make_float2(0.0f, 0.0f);
#pragma unroll
            for (int w = 0; w < NT / 32; w++) { v.x += s_w[w].x; v.y += s_w[w].y; }
            g_partials[bid] = v;
            // Release-increment orders the partial store before the bump.
            int old;
            asm volatile("atom.release.gpu.global.add.s32 %0, [%1], 1;"
                         : "=r"(old) : "l"(&g_counter) : "memory");
            last = (old == NB - 1) ? 1 : 0;
        }
        // Warp-local broadcast: no smem, no block barrier.
        last = __shfl_sync(0xFFFFFFFFu, last, 0);

        if (last) {
            // Final reduction entirely in warp 0 of the last-arriving block.
            asm volatile("fence.acquire.gpu;" ::: "memory");
            float ft = 0.0f, f0 = 0.0f;
#pragma unroll
            for (int k = 0; k < NB / 32; k++) {
                float2 pp = g_partials[k * 32 + lid];
                ft += pp.x;
                f0 += pp.y;
            }
#pragma unroll
            for (int o = 16; o > 0; o >>= 1) {
                ft += __shfl_xor_sync(0xFFFFFFFFu, ft, o);
                f0 += __shfl_xor_sync(0xFFFFFFFFu, f0, o);
            }
            if (lid == 0) {
                out[0] = ft / (float)Bc;          // sl_rhat (all t)
                out[1] = (ft - f0) / (float)Bc;   // sl_rbar (t >= 1)
                g_counter = 0;                    // reset for next graph replay
            }
        }
    }
}

extern "C" void kernel_launch(void* const* d_in, const int* in_sizes, int n_in,
                              void* d_out, int out_size)
{
    const float4* X4   = (const float4*)d_in[0];
    const float4* bsd4 = (const float4*)d_in[3];
    float* out = (float*)d_out;

    tidhy_fused_kernel<<<NB, NT>>>(X4, bsd4, out, out_size);
}